// round 12
// baseline (speedup 1.0000x reference)
#include <cuda_runtime.h>
#include <cuda_bf16.h>
#include <cstdint>
#include <math.h>

// ---------------------------------------------------------------------------
// Problem constants
// ---------------------------------------------------------------------------
#define HGT      128
#define WID      128
#define HW       (HGT * WID)
#define C_IN     256
#define DLOI     128
#define NPTS0    32
#define NPTS1    8
#define MAXLINES 16000
#define DFC      1024
#define NLAB     3

// ---------------------------------------------------------------------------
// Scratch (device globals)
// ---------------------------------------------------------------------------
__device__ __align__(256) float          g_loi [HW * DLOI];
__device__ __align__(256) __nv_bfloat16  g_feat_hi[MAXLINES * DFC];
__device__ __align__(256) __nv_bfloat16  g_feat_lo[MAXLINES * DFC];
__device__ __align__(256) __nv_bfloat16  g_x1_hi  [MAXLINES * DFC];
__device__ __align__(256) __nv_bfloat16  g_x1_lo  [MAXLINES * DFC];
__device__ __align__(256) float          g_part[8 * MAXLINES * NLAB];
__device__ __align__(256) __nv_bfloat16  g_w1_hi[DFC * DFC], g_w1_lo[DFC * DFC];
__device__ __align__(256) __nv_bfloat16  g_w2_hi[DFC * DFC], g_w2_lo[DFC * DFC];

// ---------------------------------------------------------------------------
// Portable PTX helpers (baseline sm_80+ features; compile for plain sm_103)
// ---------------------------------------------------------------------------
__device__ __forceinline__ uint32_t smem_u32(const void* p) {
    uint32_t a;
    asm("{ .reg .u64 t; cvta.to.shared.u64 t, %1; cvt.u32.u64 %0, t; }"
        : "=r"(a) : "l"(p));
    return a;
}
// SW128 swizzle (128B rows): bits[6:4] ^= bits[9:7]
#define SWZ(o) ((o) ^ (((o) >> 3) & 0x70))

__device__ __forceinline__ void cp16(uint32_t dst, const void* src) {
    asm volatile("cp.async.cg.shared.global [%0], [%1], 16;"
                 :: "r"(dst), "l"(src));
}
__device__ __forceinline__ void cp_commit() {
    asm volatile("cp.async.commit_group;");
}
__device__ __forceinline__ void ldsm4(uint32_t* r, uint32_t addr) {
    asm volatile("ldmatrix.sync.aligned.m8n8.x4.shared.b16 {%0,%1,%2,%3}, [%4];"
                 : "=r"(r[0]), "=r"(r[1]), "=r"(r[2]), "=r"(r[3]) : "r"(addr));
}
__device__ __forceinline__ void mma16816(float* c, const uint32_t* a,
                                         const uint32_t* b) {
    asm volatile(
        "mma.sync.aligned.m16n8k16.row.col.f32.bf16.bf16.f32 "
        "{%0,%1,%2,%3}, {%4,%5,%6,%7}, {%8,%9}, {%0,%1,%2,%3};"
        : "+f"(c[0]), "+f"(c[1]), "+f"(c[2]), "+f"(c[3])
        : "r"(a[0]), "r"(a[1]), "r"(a[2]), "r"(a[3]), "r"(b[0]), "r"(b[1]));
}

// ---------------------------------------------------------------------------
// Kernel 0: fp32 -> (hi, lo) bf16 plane split for BOTH weight matrices
// ---------------------------------------------------------------------------
__global__ __launch_bounds__(256) void convert_w_kernel(
    const float* __restrict__ wa, __nv_bfloat16* __restrict__ hia,
    __nv_bfloat16* __restrict__ loa,
    const float* __restrict__ wb, __nv_bfloat16* __restrict__ hib,
    __nv_bfloat16* __restrict__ lob, int nhalf)
{
    int i = (blockIdx.x * 256 + threadIdx.x) * 4;
    const float* w; __nv_bfloat16 *hi, *lo;
    if (i < nhalf) { w = wa; hi = hia; lo = loa; }
    else           { w = wb; hi = hib; lo = lob; i -= nhalf; }
    float4 v = *(const float4*)(w + i);
    __nv_bfloat162 h01(__float2bfloat16(v.x), __float2bfloat16(v.y));
    __nv_bfloat162 h23(__float2bfloat16(v.z), __float2bfloat16(v.w));
    __nv_bfloat162 l01(__float2bfloat16(v.x - __bfloat162float(h01.x)),
                       __float2bfloat16(v.y - __bfloat162float(h01.y)));
    __nv_bfloat162 l23(__float2bfloat16(v.z - __bfloat162float(h23.x)),
                       __float2bfloat16(v.w - __bfloat162float(h23.y)));
    *(uint2*)(hi + i) = make_uint2(*(uint32_t*)&h01, *(uint32_t*)&h23);
    *(uint2*)(lo + i) = make_uint2(*(uint32_t*)&l01, *(uint32_t*)&l23);
}

// ---------------------------------------------------------------------------
// Kernel 1: LOI head GEMM (SIMT)
// ---------------------------------------------------------------------------
__global__ __launch_bounds__(256) void loi_kernel(
    const float* __restrict__ features,
    const float* __restrict__ w,
    const float* __restrict__ bias,
    float* __restrict__ out)
{
    __shared__ float As[16][132];
    __shared__ float Bs[16][132];
    const int t  = threadIdx.x;
    const int m0 = blockIdx.x * 128;
    const int tx = t & 15, ty = t >> 4;

    float acc[8][8] = {};

    for (int k0 = 0; k0 < C_IN; k0 += 16) {
        #pragma unroll
        for (int i = 0; i < 2; i++) {
            int idx = t + i * 256;
            int kk  = idx >> 5;
            int c4  = (idx & 31) << 2;
            float4 v = *(const float4*)(features + (size_t)(k0 + kk) * HW + m0 + c4);
            *(float4*)(&As[kk][c4]) = v;
        }
        #pragma unroll
        for (int i = 0; i < 2; i++) {
            int idx = t + i * 256;
            int n   = idx >> 2;
            int j4  = (idx & 3) << 2;
            float4 v = *(const float4*)(w + n * C_IN + k0 + j4);
            Bs[j4 + 0][n] = v.x; Bs[j4 + 1][n] = v.y;
            Bs[j4 + 2][n] = v.z; Bs[j4 + 3][n] = v.w;
        }
        __syncthreads();
        #pragma unroll
        for (int kk = 0; kk < 16; kk++) {
            float a[8], b[8];
            *(float4*)(a)     = *(const float4*)&As[kk][ty * 8];
            *(float4*)(a + 4) = *(const float4*)&As[kk][ty * 8 + 4];
            *(float4*)(b)     = *(const float4*)&Bs[kk][tx * 8];
            *(float4*)(b + 4) = *(const float4*)&Bs[kk][tx * 8 + 4];
            #pragma unroll
            for (int i = 0; i < 8; i++)
                #pragma unroll
                for (int j = 0; j < 8; j++)
                    acc[i][j] = fmaf(a[i], b[j], acc[i][j]);
        }
        __syncthreads();
    }

    float bv[8];
    *(float4*)(bv)     = *(const float4*)(bias + tx * 8);
    *(float4*)(bv + 4) = *(const float4*)(bias + tx * 8 + 4);
    #pragma unroll
    for (int i = 0; i < 8; i++) {
        const size_t row = (size_t)(m0 + ty * 8 + i) * DLOI + tx * 8;
        float4 o0, o1;
        o0.x = fmaxf(acc[i][0] + bv[0], 0.f); o0.y = fmaxf(acc[i][1] + bv[1], 0.f);
        o0.z = fmaxf(acc[i][2] + bv[2], 0.f); o0.w = fmaxf(acc[i][3] + bv[3], 0.f);
        o1.x = fmaxf(acc[i][4] + bv[4], 0.f); o1.y = fmaxf(acc[i][5] + bv[5], 0.f);
        o1.z = fmaxf(acc[i][6] + bv[6], 0.f); o1.w = fmaxf(acc[i][7] + bv[7], 0.f);
        *(float4*)(out + row)     = o0;
        *(float4*)(out + row + 4) = o1;
    }
}

// ---------------------------------------------------------------------------
// Kernel 2: line pooling (4 warps / line; proven, near L2 floor)
// ---------------------------------------------------------------------------
__global__ __launch_bounds__(128) void pool_kernel(
    const float* __restrict__ lines,
    const float* __restrict__ loi,
    __nv_bfloat16* __restrict__ fhi,
    __nv_bfloat16* __restrict__ flo,
    int nlines)
{
    __shared__ int   s_idx[4][NPTS0];
    __shared__ float s_wgt[4][NPTS0];
    __shared__ float s_out[NPTS1][DLOI];

    const int L    = blockIdx.x;
    const int t    = threadIdx.x;
    const int w    = t >> 5;
    const int lane = t & 31;
    if (L >= nlines) return;

    if (t < NPTS0) {
        const float4 q = ((const float4*)lines)[L];
        const float tt = (float)t / 31.0f;
        const float px = q.x * tt + q.z * (1.0f - tt) - 0.5f;
        const float py = q.y * tt + q.w * (1.0f - tt) - 0.5f;
        const float px0 = fminf(fmaxf(floorf(px), 0.0f), 127.0f);
        const float py0 = fminf(fmaxf(floorf(py), 0.0f), 127.0f);
        const float px1 = fminf(px0 + 1.0f, 127.0f);
        const float py1 = fminf(py0 + 1.0f, 127.0f);
        const int ix0 = (int)px0, iy0 = (int)py0, ix1 = (int)px1, iy1 = (int)py1;
        s_idx[0][t] = (iy0 * WID + ix0) * DLOI;
        s_idx[1][t] = (iy1 * WID + ix0) * DLOI;
        s_idx[2][t] = (iy0 * WID + ix1) * DLOI;
        s_idx[3][t] = (iy1 * WID + ix1) * DLOI;
        const float wy0 = py1 - py, wy1 = py - py0;
        const float wx0 = px1 - px, wx1 = px - px0;
        s_wgt[0][t] = wy0 * wx0;
        s_wgt[1][t] = wy1 * wx0;
        s_wgt[2][t] = wy0 * wx1;
        s_wgt[3][t] = wy1 * wx1;
    }
    __syncthreads();

    const int c4 = lane * 4;
    #pragma unroll
    for (int pp = 0; pp < 2; pp++) {
        const int p = w * 2 + pp;
        float mx = -1e30f, my = -1e30f, mz = -1e30f, mw = -1e30f;
        #pragma unroll
        for (int k = 0; k < 4; k++) {
            const int j = p * 4 + k;
            const int   i00 = s_idx[0][j], i10 = s_idx[1][j];
            const int   i01 = s_idx[2][j], i11 = s_idx[3][j];
            const float w00 = s_wgt[0][j], w10 = s_wgt[1][j];
            const float w01 = s_wgt[2][j], w11 = s_wgt[3][j];
            const float4 v00 = *(const float4*)(loi + i00 + c4);
            const float4 v10 = *(const float4*)(loi + i10 + c4);
            const float4 v01 = *(const float4*)(loi + i01 + c4);
            const float4 v11 = *(const float4*)(loi + i11 + c4);
            float vx, vy, vz, vw;
            vx = fmaf(w00, v00.x, fmaf(w10, v10.x, fmaf(w01, v01.x, w11 * v11.x)));
            vy = fmaf(w00, v00.y, fmaf(w10, v10.y, fmaf(w01, v01.y, w11 * v11.y)));
            vz = fmaf(w00, v00.z, fmaf(w10, v10.z, fmaf(w01, v01.z, w11 * v11.z)));
            vw = fmaf(w00, v00.w, fmaf(w10, v10.w, fmaf(w01, v01.w, w11 * v11.w)));
            mx = fmaxf(mx, vx); my = fmaxf(my, vy);
            mz = fmaxf(mz, vz); mw = fmaxf(mw, vw);
        }
        *(float4*)(&s_out[p][c4]) = make_float4(mx, my, mz, mw);
    }
    __syncthreads();

    __nv_bfloat16 h[NPTS1], l[NPTS1];
    #pragma unroll
    for (int p = 0; p < NPTS1; p++) {
        const float v = s_out[p][t];
        __nv_bfloat16 hb = __float2bfloat16(v);
        h[p] = hb;
        l[p] = __float2bfloat16(v - __bfloat162float(hb));
    }
    const size_t off = (size_t)L * DFC + t * NPTS1;
    *(uint4*)(fhi + off) = *(uint4*)h;
    *(uint4*)(flo + off) = *(uint4*)l;
}

// ---------------------------------------------------------------------------
// Kernel 3: HMMA split-precision FC layer, 512 threads (16 warps, 4x4 grid).
//   Proven SW128 / KC=64 / 3-stage pipeline; warp tile 32x32.
//   MODE 1: out = hi/lo bf16 planes (fc1).
//   MODE 2: fused final layer — per-block partial logits (fc2+fc3).
// ---------------------------------------------------------------------------
#define KC      64
#define TILEB   16384            // 128 rows x 128B (64 bf16)
#define BUFB    (4 * TILEB)      // A_hi, A_lo, W_hi, W_lo
#define NSTAGE  3
#define SMEM_FC (1024 + NSTAGE * BUFB)
#define FC_THR  512

template<int MODE>
__global__ __launch_bounds__(FC_THR, 1)
void fc_mma_kernel(const __nv_bfloat16* __restrict__ Ahi,
                   const __nv_bfloat16* __restrict__ Alo,
                   const __nv_bfloat16* __restrict__ Whi,
                   const __nv_bfloat16* __restrict__ Wlo,
                   const float* __restrict__ bias,
                   __nv_bfloat16* __restrict__ Chi,
                   __nv_bfloat16* __restrict__ Clo,
                   const float* __restrict__ w3,
                   float* __restrict__ part,
                   int M, int N, int K)
{
    extern __shared__ char smem_raw[];
    const uint32_t sb   = smem_u32(smem_raw);
    const uint32_t bufu = (sb + 1023) & ~1023u;
    char* bufbase = smem_raw + (bufu - sb);

    const int t     = threadIdx.x;
    const int warp  = t >> 5, lane = t & 31;
    const int warpM = warp & 3;          // 4 warps along M (32 rows each)
    const int warpN = warp >> 2;         // 4 warps along N (32 cols each)
    const int m0    = blockIdx.x * 128;
    const int n0    = blockIdx.y * 128;

    // A fragment lanes (row % 8 == lane % 8 -> axor valid)
    const int ar  = (lane & 7) + ((lane >> 3) & 1) * 8;
    const int acb = ((lane >> 4) & 1) * 16;
    const uint32_t axor = (uint32_t)((lane & 7) << 4);
    uint32_t aterm[2];
    #pragma unroll
    for (int mt = 0; mt < 2; mt++)
        aterm[mt] = (uint32_t)((warpM * 32 + mt * 16 + ar) * 128);
    // B fragment lanes
    const int bi  = lane >> 3;
    const int bcb = (bi & 1) * 16;
    uint32_t bterm[2];
    #pragma unroll
    for (int p = 0; p < 2; p++)
        bterm[p] = (uint32_t)((warpN * 32 + (2 * p + (bi >> 1)) * 8 + (lane & 7)) * 128);

    float acc[2][4][4] = {};

    auto load_chunk = [&](int c) {
        const uint32_t dbase = bufu + (uint32_t)(c % NSTAGE) * BUFB;
        const int k0 = c * KC;
        #pragma unroll
        for (int i = 0; i < 2; i++) {
            const int idx = t + i * FC_THR;        // 0..1023 granules/plane
            const int row = idx >> 3, g8 = (idx & 7) * 8;
            const uint32_t off = SWZ((uint32_t)(row * 128 + g8 * 2));
            const size_t ga = (size_t)(m0 + row) * K + k0 + g8;
            const size_t gw = (size_t)(n0 + row) * K + k0 + g8;
            cp16(dbase + off,             Ahi + ga);
            cp16(dbase + TILEB + off,     Alo + ga);
            cp16(dbase + 2 * TILEB + off, Whi + gw);
            cp16(dbase + 3 * TILEB + off, Wlo + gw);
        }
        cp_commit();
    };

    const int nchunk = K / KC;   // 16
    load_chunk(0);
    load_chunk(1);

    for (int c = 0; c < nchunk; ++c) {
        if (c + 1 < nchunk) asm volatile("cp.async.wait_group 1;");
        else                asm volatile("cp.async.wait_group 0;");
        __syncthreads();
        if (c + 2 < nchunk) load_chunk(c + 2);

        const uint32_t base = bufu + (uint32_t)(c % NSTAGE) * BUFB;
        #pragma unroll
        for (int kk = 0; kk < 4; kk++) {
            const uint32_t acol = (uint32_t)(kk * 32 + acb) ^ axor;
            const uint32_t bcol = (uint32_t)(kk * 32 + bcb) ^ axor;

            uint32_t aF[2][4], bH[2][4], bL[2][4];
            #pragma unroll
            for (int mt = 0; mt < 2; mt++)
                ldsm4(aF[mt], base + aterm[mt] + acol);              // A_hi
            #pragma unroll
            for (int p = 0; p < 2; p++) {
                ldsm4(bH[p], base + 2 * TILEB + bterm[p] + bcol);    // W_hi
                ldsm4(bL[p], base + 3 * TILEB + bterm[p] + bcol);    // W_lo
            }
            #pragma unroll
            for (int mt = 0; mt < 2; mt++)
                #pragma unroll
                for (int nt = 0; nt < 4; nt++) {
                    mma16816(acc[mt][nt], aF[mt], &bH[nt >> 1][(nt & 1) * 2]);
                    mma16816(acc[mt][nt], aF[mt], &bL[nt >> 1][(nt & 1) * 2]);
                }
            #pragma unroll
            for (int mt = 0; mt < 2; mt++)
                ldsm4(aF[mt], base + TILEB + aterm[mt] + acol);      // A_lo
            #pragma unroll
            for (int mt = 0; mt < 2; mt++)
                #pragma unroll
                for (int nt = 0; nt < 4; nt++)
                    mma16816(acc[mt][nt], aF[mt], &bH[nt >> 1][(nt & 1) * 2]);
        }
    }

    const int qrow = lane >> 2;
    const int qcol = (lane & 3) * 2;

    if (MODE == 1) {
        #pragma unroll
        for (int nt = 0; nt < 4; nt++) {
            const int coln = n0 + warpN * 32 + nt * 8 + qcol;
            const float2 bv = *(const float2*)(bias + coln);
            #pragma unroll
            for (int mt = 0; mt < 2; mt++) {
                const int rown = m0 + warpM * 32 + mt * 16 + qrow;
                float v0 = fmaxf(acc[mt][nt][0] + bv.x, 0.f);
                float v1 = fmaxf(acc[mt][nt][1] + bv.y, 0.f);
                float v2 = fmaxf(acc[mt][nt][2] + bv.x, 0.f);
                float v3 = fmaxf(acc[mt][nt][3] + bv.y, 0.f);
                const size_t o0 = (size_t)rown * N + coln;
                const size_t o1 = (size_t)(rown + 8) * N + coln;
                __nv_bfloat162 h0(__float2bfloat16(v0), __float2bfloat16(v1));
                __nv_bfloat162 h1(__float2bfloat16(v2), __float2bfloat16(v3));
                __nv_bfloat162 l0(__float2bfloat16(v0 - __bfloat162float(h0.x)),
                                  __float2bfloat16(v1 - __bfloat162float(h0.y)));
                __nv_bfloat162 l1(__float2bfloat16(v2 - __bfloat162float(h1.x)),
                                  __float2bfloat16(v3 - __bfloat162float(h1.y)));
                *(uint32_t*)(Chi + o0) = *(uint32_t*)&h0;
                *(uint32_t*)(Chi + o1) = *(uint32_t*)&h1;
                *(uint32_t*)(Clo + o0) = *(uint32_t*)&l0;
                *(uint32_t*)(Clo + o1) = *(uint32_t*)&l1;
            }
        }
    } else {
        __syncthreads();    // all compute done before smem reuse
        float pr[2][2][3] = {};
        #pragma unroll
        for (int nt = 0; nt < 4; nt++) {
            const int coln = n0 + warpN * 32 + nt * 8 + qcol;
            const float2 bv = *(const float2*)(bias + coln);
            float w3v[3][2];
            #pragma unroll
            for (int lab = 0; lab < 3; lab++) {
                w3v[lab][0] = w3[lab * DFC + coln];
                w3v[lab][1] = w3[lab * DFC + coln + 1];
            }
            #pragma unroll
            for (int mt = 0; mt < 2; mt++) {
                float v0 = fmaxf(acc[mt][nt][0] + bv.x, 0.f);
                float v1 = fmaxf(acc[mt][nt][1] + bv.y, 0.f);
                float v2 = fmaxf(acc[mt][nt][2] + bv.x, 0.f);
                float v3 = fmaxf(acc[mt][nt][3] + bv.y, 0.f);
                #pragma unroll
                for (int lab = 0; lab < 3; lab++) {
                    pr[mt][0][lab] = fmaf(v0, w3v[lab][0],
                                     fmaf(v1, w3v[lab][1], pr[mt][0][lab]));
                    pr[mt][1][lab] = fmaf(v2, w3v[lab][0],
                                     fmaf(v3, w3v[lab][1], pr[mt][1][lab]));
                }
            }
        }
        // reduce over the 4 qcol lanes (same qrow)
        #pragma unroll
        for (int mask = 1; mask <= 2; mask <<= 1)
            #pragma unroll
            for (int mt = 0; mt < 2; mt++)
                #pragma unroll
                for (int hh = 0; hh < 2; hh++)
                    #pragma unroll
                    for (int lab = 0; lab < 3; lab++)
                        pr[mt][hh][lab] +=
                            __shfl_xor_sync(0xffffffffu, pr[mt][hh][lab], mask);
        float* ps = (float*)bufbase;   // [4 warpN][128 m][3]
        if ((lane & 3) == 0) {
            #pragma unroll
            for (int mt = 0; mt < 2; mt++)
                #pragma unroll
                for (int hh = 0; hh < 2; hh++) {
                    const int ml = warpM * 32 + mt * 16 + hh * 8 + qrow;
                    #pragma unroll
                    for (int lab = 0; lab < 3; lab++)
                        ps[(warpN * 128 + ml) * 3 + lab] = pr[mt][hh][lab];
                }
        }
        __syncthreads();
        if (t < 384) {
            const int ml = t / 3, lab = t - ml * 3;
            const float s = ps[ml * 3 + lab] + ps[(128 + ml) * 3 + lab]
                          + ps[(256 + ml) * 3 + lab] + ps[(384 + ml) * 3 + lab];
            part[(size_t)blockIdx.y * M * 3 + (size_t)(m0 + ml) * 3 + lab] = s;
        }
    }
}

// ---------------------------------------------------------------------------
// Kernel 4: deterministic partial-logit reduction (+b3)
// ---------------------------------------------------------------------------
__global__ __launch_bounds__(256) void logits_kernel(
    const float* __restrict__ part,
    const float* __restrict__ b3,
    float* __restrict__ out, int M)
{
    const int idx = blockIdx.x * 256 + threadIdx.x;
    if (idx >= M * 3) return;
    const int lab = idx % 3;
    float s = b3[lab];
    #pragma unroll
    for (int by = 0; by < 8; by++)
        s += part[(size_t)by * M * 3 + idx];
    out[idx] = s;
}

// ---------------------------------------------------------------------------
// Launcher
// ---------------------------------------------------------------------------
extern "C" void kernel_launch(void* const* d_in, const int* in_sizes, int n_in,
                              void* d_out, int out_size)
{
    const float* features = (const float*)d_in[0];
    const float* lines    = (const float*)d_in[1];
    const float* w_fc1    = (const float*)d_in[2];
    const float* b_fc1    = (const float*)d_in[3];
    const float* w1       = (const float*)d_in[4];
    const float* b1       = (const float*)d_in[5];
    const float* w2       = (const float*)d_in[6];
    const float* b2       = (const float*)d_in[7];
    const float* w3       = (const float*)d_in[8];
    const float* b3       = (const float*)d_in[9];
    float* out = (float*)d_out;

    const int nlines = in_sizes[1] / 4;   // 16000

    float *loi, *part;
    __nv_bfloat16 *fhi, *flo, *x1hi, *x1lo, *w1hi, *w1lo, *w2hi, *w2lo;
    cudaGetSymbolAddress((void**)&loi,  g_loi);
    cudaGetSymbolAddress((void**)&fhi,  g_feat_hi);
    cudaGetSymbolAddress((void**)&flo,  g_feat_lo);
    cudaGetSymbolAddress((void**)&x1hi, g_x1_hi);
    cudaGetSymbolAddress((void**)&x1lo, g_x1_lo);
    cudaGetSymbolAddress((void**)&part, g_part);
    cudaGetSymbolAddress((void**)&w1hi, g_w1_hi);
    cudaGetSymbolAddress((void**)&w1lo, g_w1_lo);
    cudaGetSymbolAddress((void**)&w2hi, g_w2_hi);
    cudaGetSymbolAddress((void**)&w2lo, g_w2_lo);

    cudaFuncSetAttribute(fc_mma_kernel<1>,
                         cudaFuncAttributeMaxDynamicSharedMemorySize, SMEM_FC);
    cudaFuncSetAttribute(fc_mma_kernel<2>,
                         cudaFuncAttributeMaxDynamicSharedMemorySize, SMEM_FC);

    // 0. weight split planes (single launch for both)
    convert_w_kernel<<<2 * DFC * DFC / 1024, 256>>>(
        w1, w1hi, w1lo, w2, w2hi, w2lo, DFC * DFC);

    // 1. LOI head
    loi_kernel<<<HW / 128, 256>>>(features, w_fc1, b_fc1, loi);

    // 2. Line pooling -> split planes
    pool_kernel<<<nlines, 128>>>(lines, loi, fhi, flo, nlines);

    // 3. MLP on tensor cores; fc2 fuses the 3-label output layer
    const int mb = nlines / 128;          // 125
    fc_mma_kernel<1><<<dim3(mb, DFC / 128), FC_THR, SMEM_FC>>>(
        fhi, flo, w1hi, w1lo, b1, x1hi, x1lo, nullptr, nullptr, nlines, DFC, DFC);
    fc_mma_kernel<2><<<dim3(mb, DFC / 128), FC_THR, SMEM_FC>>>(
        x1hi, x1lo, w2hi, w2lo, b2, nullptr, nullptr, w3, part, nlines, DFC, DFC);

    // 4. Reduce partials -> logits
    logits_kernel<<<(nlines * 3 + 255) / 256, 256>>>(part, b3, out, nlines);
}

// round 13
// speedup vs baseline: 1.3627x; 1.3627x over previous
#include <cuda_runtime.h>
#include <cuda_fp16.h>
#include <cstdint>
#include <math.h>

// ---------------------------------------------------------------------------
// Problem constants
// ---------------------------------------------------------------------------
#define HGT      128
#define WID      128
#define HW       (HGT * WID)
#define C_IN     256
#define DLOI     128
#define NPTS0    32
#define NPTS1    8
#define MAXLINES 16000
#define DFC      1024
#define NLAB     3

// ---------------------------------------------------------------------------
// Scratch (device globals)
// ---------------------------------------------------------------------------
__device__ __align__(256) float   g_loi [HW * DLOI];
__device__ __align__(256) __half  g_feat_hi[MAXLINES * DFC];
__device__ __align__(256) __half  g_feat_lo[MAXLINES * DFC];
__device__ __align__(256) __half  g_x1_hi  [MAXLINES * DFC];
__device__ __align__(256) __half  g_x1_lo  [MAXLINES * DFC];
__device__ __align__(256) float   g_part[8 * MAXLINES * NLAB];
__device__ __align__(256) __half  g_w1h[DFC * DFC];
__device__ __align__(256) __half  g_w2h[DFC * DFC];

// ---------------------------------------------------------------------------
// Portable PTX helpers (baseline sm_80+ features; compile for plain sm_103)
// ---------------------------------------------------------------------------
__device__ __forceinline__ uint32_t smem_u32(const void* p) {
    uint32_t a;
    asm("{ .reg .u64 t; cvta.to.shared.u64 t, %1; cvt.u32.u64 %0, t; }"
        : "=r"(a) : "l"(p));
    return a;
}
// SW128 swizzle (128B rows): bits[6:4] ^= bits[9:7]
#define SWZ(o) ((o) ^ (((o) >> 3) & 0x70))

__device__ __forceinline__ void cp16(uint32_t dst, const void* src) {
    asm volatile("cp.async.cg.shared.global [%0], [%1], 16;"
                 :: "r"(dst), "l"(src));
}
__device__ __forceinline__ void cp_commit() {
    asm volatile("cp.async.commit_group;");
}
__device__ __forceinline__ void ldsm4(uint32_t* r, uint32_t addr) {
    asm volatile("ldmatrix.sync.aligned.m8n8.x4.shared.b16 {%0,%1,%2,%3}, [%4];"
                 : "=r"(r[0]), "=r"(r[1]), "=r"(r[2]), "=r"(r[3]) : "r"(addr));
}
__device__ __forceinline__ void mma16816(float* c, const uint32_t* a,
                                         const uint32_t* b) {
    asm volatile(
        "mma.sync.aligned.m16n8k16.row.col.f32.f16.f16.f32 "
        "{%0,%1,%2,%3}, {%4,%5,%6,%7}, {%8,%9}, {%0,%1,%2,%3};"
        : "+f"(c[0]), "+f"(c[1]), "+f"(c[2]), "+f"(c[3])
        : "r"(a[0]), "r"(a[1]), "r"(a[2]), "r"(a[3]), "r"(b[0]), "r"(b[1]));
}

// ---------------------------------------------------------------------------
// Kernel 0: fp32 -> single fp16 plane for BOTH weight matrices
// ---------------------------------------------------------------------------
__global__ __launch_bounds__(256) void convert_w_kernel(
    const float* __restrict__ wa, __half* __restrict__ ha,
    const float* __restrict__ wb, __half* __restrict__ hb, int nhalf)
{
    int i = (blockIdx.x * 256 + threadIdx.x) * 4;
    const float* w; __half* h;
    if (i < nhalf) { w = wa; h = ha; }
    else           { w = wb; h = hb; i -= nhalf; }
    float4 v = *(const float4*)(w + i);
    __half2 p0 = __floats2half2_rn(v.x, v.y);
    __half2 p1 = __floats2half2_rn(v.z, v.w);
    *(uint2*)(h + i) = make_uint2(*(uint32_t*)&p0, *(uint32_t*)&p1);
}

// ---------------------------------------------------------------------------
// Kernel 1: LOI head GEMM (SIMT)
// ---------------------------------------------------------------------------
__global__ __launch_bounds__(256) void loi_kernel(
    const float* __restrict__ features,
    const float* __restrict__ w,
    const float* __restrict__ bias,
    float* __restrict__ out)
{
    __shared__ float As[16][132];
    __shared__ float Bs[16][132];
    const int t  = threadIdx.x;
    const int m0 = blockIdx.x * 128;
    const int tx = t & 15, ty = t >> 4;

    float acc[8][8] = {};

    for (int k0 = 0; k0 < C_IN; k0 += 16) {
        #pragma unroll
        for (int i = 0; i < 2; i++) {
            int idx = t + i * 256;
            int kk  = idx >> 5;
            int c4  = (idx & 31) << 2;
            float4 v = *(const float4*)(features + (size_t)(k0 + kk) * HW + m0 + c4);
            *(float4*)(&As[kk][c4]) = v;
        }
        #pragma unroll
        for (int i = 0; i < 2; i++) {
            int idx = t + i * 256;
            int n   = idx >> 2;
            int j4  = (idx & 3) << 2;
            float4 v = *(const float4*)(w + n * C_IN + k0 + j4);
            Bs[j4 + 0][n] = v.x; Bs[j4 + 1][n] = v.y;
            Bs[j4 + 2][n] = v.z; Bs[j4 + 3][n] = v.w;
        }
        __syncthreads();
        #pragma unroll
        for (int kk = 0; kk < 16; kk++) {
            float a[8], b[8];
            *(float4*)(a)     = *(const float4*)&As[kk][ty * 8];
            *(float4*)(a + 4) = *(const float4*)&As[kk][ty * 8 + 4];
            *(float4*)(b)     = *(const float4*)&Bs[kk][tx * 8];
            *(float4*)(b + 4) = *(const float4*)&Bs[kk][tx * 8 + 4];
            #pragma unroll
            for (int i = 0; i < 8; i++)
                #pragma unroll
                for (int j = 0; j < 8; j++)
                    acc[i][j] = fmaf(a[i], b[j], acc[i][j]);
        }
        __syncthreads();
    }

    float bv[8];
    *(float4*)(bv)     = *(const float4*)(bias + tx * 8);
    *(float4*)(bv + 4) = *(const float4*)(bias + tx * 8 + 4);
    #pragma unroll
    for (int i = 0; i < 8; i++) {
        const size_t row = (size_t)(m0 + ty * 8 + i) * DLOI + tx * 8;
        float4 o0, o1;
        o0.x = fmaxf(acc[i][0] + bv[0], 0.f); o0.y = fmaxf(acc[i][1] + bv[1], 0.f);
        o0.z = fmaxf(acc[i][2] + bv[2], 0.f); o0.w = fmaxf(acc[i][3] + bv[3], 0.f);
        o1.x = fmaxf(acc[i][4] + bv[4], 0.f); o1.y = fmaxf(acc[i][5] + bv[5], 0.f);
        o1.z = fmaxf(acc[i][6] + bv[6], 0.f); o1.w = fmaxf(acc[i][7] + bv[7], 0.f);
        *(float4*)(out + row)     = o0;
        *(float4*)(out + row + 4) = o1;
    }
}

// ---------------------------------------------------------------------------
// Kernel 2: line pooling (4 warps / line; proven) -> fp16 hi/lo planes
// ---------------------------------------------------------------------------
__global__ __launch_bounds__(128) void pool_kernel(
    const float* __restrict__ lines,
    const float* __restrict__ loi,
    __half* __restrict__ fhi,
    __half* __restrict__ flo,
    int nlines)
{
    __shared__ int   s_idx[4][NPTS0];
    __shared__ float s_wgt[4][NPTS0];
    __shared__ float s_out[NPTS1][DLOI];

    const int L    = blockIdx.x;
    const int t    = threadIdx.x;
    const int w    = t >> 5;
    const int lane = t & 31;
    if (L >= nlines) return;

    if (t < NPTS0) {
        const float4 q = ((const float4*)lines)[L];
        const float tt = (float)t / 31.0f;
        const float px = q.x * tt + q.z * (1.0f - tt) - 0.5f;
        const float py = q.y * tt + q.w * (1.0f - tt) - 0.5f;
        const float px0 = fminf(fmaxf(floorf(px), 0.0f), 127.0f);
        const float py0 = fminf(fmaxf(floorf(py), 0.0f), 127.0f);
        const float px1 = fminf(px0 + 1.0f, 127.0f);
        const float py1 = fminf(py0 + 1.0f, 127.0f);
        const int ix0 = (int)px0, iy0 = (int)py0, ix1 = (int)px1, iy1 = (int)py1;
        s_idx[0][t] = (iy0 * WID + ix0) * DLOI;
        s_idx[1][t] = (iy1 * WID + ix0) * DLOI;
        s_idx[2][t] = (iy0 * WID + ix1) * DLOI;
        s_idx[3][t] = (iy1 * WID + ix1) * DLOI;
        const float wy0 = py1 - py, wy1 = py - py0;
        const float wx0 = px1 - px, wx1 = px - px0;
        s_wgt[0][t] = wy0 * wx0;
        s_wgt[1][t] = wy1 * wx0;
        s_wgt[2][t] = wy0 * wx1;
        s_wgt[3][t] = wy1 * wx1;
    }
    __syncthreads();

    const int c4 = lane * 4;
    #pragma unroll
    for (int pp = 0; pp < 2; pp++) {
        const int p = w * 2 + pp;
        float mx = -1e30f, my = -1e30f, mz = -1e30f, mw = -1e30f;
        #pragma unroll
        for (int k = 0; k < 4; k++) {
            const int j = p * 4 + k;
            const int   i00 = s_idx[0][j], i10 = s_idx[1][j];
            const int   i01 = s_idx[2][j], i11 = s_idx[3][j];
            const float w00 = s_wgt[0][j], w10 = s_wgt[1][j];
            const float w01 = s_wgt[2][j], w11 = s_wgt[3][j];
            const float4 v00 = *(const float4*)(loi + i00 + c4);
            const float4 v10 = *(const float4*)(loi + i10 + c4);
            const float4 v01 = *(const float4*)(loi + i01 + c4);
            const float4 v11 = *(const float4*)(loi + i11 + c4);
            float vx, vy, vz, vw;
            vx = fmaf(w00, v00.x, fmaf(w10, v10.x, fmaf(w01, v01.x, w11 * v11.x)));
            vy = fmaf(w00, v00.y, fmaf(w10, v10.y, fmaf(w01, v01.y, w11 * v11.y)));
            vz = fmaf(w00, v00.z, fmaf(w10, v10.z, fmaf(w01, v01.z, w11 * v11.z)));
            vw = fmaf(w00, v00.w, fmaf(w10, v10.w, fmaf(w01, v01.w, w11 * v11.w)));
            mx = fmaxf(mx, vx); my = fmaxf(my, vy);
            mz = fmaxf(mz, vz); mw = fmaxf(mw, vw);
        }
        *(float4*)(&s_out[p][c4]) = make_float4(mx, my, mz, mw);
    }
    __syncthreads();

    __half h[NPTS1], l[NPTS1];
    #pragma unroll
    for (int p = 0; p < NPTS1; p++) {
        const float v = s_out[p][t];
        __half hb = __float2half_rn(v);
        h[p] = hb;
        l[p] = __float2half_rn(v - __half2float(hb));
    }
    const size_t off = (size_t)L * DFC + t * NPTS1;
    *(uint4*)(fhi + off) = *(uint4*)h;
    *(uint4*)(flo + off) = *(uint4*)l;
}

// ---------------------------------------------------------------------------
// Kernel 3: HMMA fp16 FC layer. A = hi/lo fp16 (exact), W = single fp16.
//   D = Ahi*W + Alo*W  (fp32 accum). 256 thr, 8 warps (2M x 4N), tile 64x32.
//   SW128 / KC=64 / 3-stage cp.async pipeline (proven).
//   MODE 1: out = hi/lo fp16 planes (fc1).
//   MODE 2: fused final layer — per-block partial logits (fc2+fc3).
// ---------------------------------------------------------------------------
#define KC      64
#define TILEB   16384            // 128 rows x 128B (64 fp16)
#define BUFB    (3 * TILEB)      // A_hi, A_lo, W
#define NSTAGE  3
#define SMEM_FC (1024 + NSTAGE * BUFB)

template<int MODE>
__global__ __launch_bounds__(256, 1)
void fc_mma_kernel(const __half* __restrict__ Ahi,
                   const __half* __restrict__ Alo,
                   const __half* __restrict__ W,
                   const float* __restrict__ bias,
                   __half* __restrict__ Chi,
                   __half* __restrict__ Clo,
                   const float* __restrict__ w3,
                   float* __restrict__ part,
                   int M, int N, int K)
{
    extern __shared__ char smem_raw[];
    const uint32_t sb   = smem_u32(smem_raw);
    const uint32_t bufu = (sb + 1023) & ~1023u;
    char* bufbase = smem_raw + (bufu - sb);

    const int t     = threadIdx.x;
    const int warp  = t >> 5, lane = t & 31;
    const int warpM = warp & 1;          // 2 warps along M (64 rows)
    const int warpN = warp >> 1;         // 4 warps along N (32 cols)
    const int m0    = blockIdx.x * 128;
    const int n0    = blockIdx.y * 128;

    const int ar   = (lane & 7) + ((lane >> 3) & 1) * 8;
    const int acb  = ((lane >> 4) & 1) * 16;
    const uint32_t axor = (uint32_t)((lane & 7) << 4);
    uint32_t aterm[4];
    #pragma unroll
    for (int mt = 0; mt < 4; mt++)
        aterm[mt] = (uint32_t)((warpM * 64 + mt * 16 + ar) * 128);
    const int bi  = lane >> 3;
    const int bcb = (bi & 1) * 16;
    uint32_t bterm[2];
    #pragma unroll
    for (int p = 0; p < 2; p++)
        bterm[p] = (uint32_t)((warpN * 32 + (2 * p + (bi >> 1)) * 8 + (lane & 7)) * 128);

    float acc[4][4][4] = {};

    auto load_chunk = [&](int c) {
        const uint32_t dbase = bufu + (uint32_t)(c % NSTAGE) * BUFB;
        const int k0 = c * KC;
        #pragma unroll
        for (int i = 0; i < 4; i++) {
            const int idx = t + i * 256;
            const int row = idx >> 3, g8 = (idx & 7) * 8;
            const uint32_t off = SWZ((uint32_t)(row * 128 + g8 * 2));
            const size_t ga = (size_t)(m0 + row) * K + k0 + g8;
            const size_t gw = (size_t)(n0 + row) * K + k0 + g8;
            cp16(dbase + off,             Ahi + ga);
            cp16(dbase + TILEB + off,     Alo + ga);
            cp16(dbase + 2 * TILEB + off, W + gw);
        }
        cp_commit();
    };

    const int nchunk = K / KC;   // 16
    load_chunk(0);
    load_chunk(1);

    for (int c = 0; c < nchunk; ++c) {
        if (c + 1 < nchunk) asm volatile("cp.async.wait_group 1;");
        else                asm volatile("cp.async.wait_group 0;");
        __syncthreads();
        if (c + 2 < nchunk) load_chunk(c + 2);

        const uint32_t base = bufu + (uint32_t)(c % NSTAGE) * BUFB;
        #pragma unroll
        for (int kk = 0; kk < 4; kk++) {
            const uint32_t acol = (uint32_t)(kk * 32 + acb) ^ axor;
            const uint32_t bcol = (uint32_t)(kk * 32 + bcb) ^ axor;

            uint32_t aH[4][4], aL[4][4], bW[2][4];
            // issue ALL fragment loads up-front for max LDSM/HMMA overlap
            #pragma unroll
            for (int mt = 0; mt < 4; mt++)
                ldsm4(aH[mt], base + aterm[mt] + acol);
            #pragma unroll
            for (int p = 0; p < 2; p++)
                ldsm4(bW[p], base + 2 * TILEB + bterm[p] + bcol);
            #pragma unroll
            for (int mt = 0; mt < 4; mt++)
                ldsm4(aL[mt], base + TILEB + aterm[mt] + acol);

            #pragma unroll
            for (int mt = 0; mt < 4; mt++)
                #pragma unroll
                for (int nt = 0; nt < 4; nt++)
                    mma16816(acc[mt][nt], aH[mt], &bW[nt >> 1][(nt & 1) * 2]);
            #pragma unroll
            for (int mt = 0; mt < 4; mt++)
                #pragma unroll
                for (int nt = 0; nt < 4; nt++)
                    mma16816(acc[mt][nt], aL[mt], &bW[nt >> 1][(nt & 1) * 2]);
        }
    }

    const int qrow = lane >> 2;
    const int qcol = (lane & 3) * 2;

    if (MODE == 1) {
        #pragma unroll
        for (int nt = 0; nt < 4; nt++) {
            const int coln = n0 + warpN * 32 + nt * 8 + qcol;
            const float2 bv = *(const float2*)(bias + coln);
            #pragma unroll
            for (int mt = 0; mt < 4; mt++) {
                const int rown = m0 + warpM * 64 + mt * 16 + qrow;
                float v0 = fmaxf(acc[mt][nt][0] + bv.x, 0.f);
                float v1 = fmaxf(acc[mt][nt][1] + bv.y, 0.f);
                float v2 = fmaxf(acc[mt][nt][2] + bv.x, 0.f);
                float v3 = fmaxf(acc[mt][nt][3] + bv.y, 0.f);
                const size_t o0 = (size_t)rown * N + coln;
                const size_t o1 = (size_t)(rown + 8) * N + coln;
                __half h0 = __float2half_rn(v0), h1 = __float2half_rn(v1);
                __half h2 = __float2half_rn(v2), h3 = __float2half_rn(v3);
                __half l0 = __float2half_rn(v0 - __half2float(h0));
                __half l1 = __float2half_rn(v1 - __half2float(h1));
                __half l2 = __float2half_rn(v2 - __half2float(h2));
                __half l3 = __float2half_rn(v3 - __half2float(h3));
                __half2 ph0, ph1, pl0, pl1;
                ph0.x = h0; ph0.y = h1; ph1.x = h2; ph1.y = h3;
                pl0.x = l0; pl0.y = l1; pl1.x = l2; pl1.y = l3;
                *(__half2*)(Chi + o0) = ph0;
                *(__half2*)(Chi + o1) = ph1;
                *(__half2*)(Clo + o0) = pl0;
                *(__half2*)(Clo + o1) = pl1;
            }
        }
    } else {
        __syncthreads();    // all compute done before smem reuse
        float pr[4][2][3] = {};
        #pragma unroll
        for (int nt = 0; nt < 4; nt++) {
            const int coln = n0 + warpN * 32 + nt * 8 + qcol;
            const float2 bv = *(const float2*)(bias + coln);
            float w3v[3][2];
            #pragma unroll
            for (int lab = 0; lab < 3; lab++) {
                w3v[lab][0] = w3[lab * DFC + coln];
                w3v[lab][1] = w3[lab * DFC + coln + 1];
            }
            #pragma unroll
            for (int mt = 0; mt < 4; mt++) {
                float v0 = fmaxf(acc[mt][nt][0] + bv.x, 0.f);
                float v1 = fmaxf(acc[mt][nt][1] + bv.y, 0.f);
                float v2 = fmaxf(acc[mt][nt][2] + bv.x, 0.f);
                float v3 = fmaxf(acc[mt][nt][3] + bv.y, 0.f);
                #pragma unroll
                for (int lab = 0; lab < 3; lab++) {
                    pr[mt][0][lab] = fmaf(v0, w3v[lab][0],
                                     fmaf(v1, w3v[lab][1], pr[mt][0][lab]));
                    pr[mt][1][lab] = fmaf(v2, w3v[lab][0],
                                     fmaf(v3, w3v[lab][1], pr[mt][1][lab]));
                }
            }
        }
        #pragma unroll
        for (int mask = 1; mask <= 2; mask <<= 1)
            #pragma unroll
            for (int mt = 0; mt < 4; mt++)
                #pragma unroll
                for (int hh = 0; hh < 2; hh++)
                    #pragma unroll
                    for (int lab = 0; lab < 3; lab++)
                        pr[mt][hh][lab] +=
                            __shfl_xor_sync(0xffffffffu, pr[mt][hh][lab], mask);
        float* ps = (float*)bufbase;   // [4 warpN][128 m][3]
        if ((lane & 3) == 0) {
            #pragma unroll
            for (int mt = 0; mt < 4; mt++)
                #pragma unroll
                for (int hh = 0; hh < 2; hh++) {
                    const int ml = warpM * 64 + mt * 16 + hh * 8 + qrow;
                    #pragma unroll
                    for (int lab = 0; lab < 3; lab++)
                        ps[(warpN * 128 + ml) * 3 + lab] = pr[mt][hh][lab];
                }
        }
        __syncthreads();
        for (int idx = t; idx < 384; idx += 256) {
            const int ml = idx / 3, lab = idx - ml * 3;
            const float s = ps[ml * 3 + lab] + ps[(128 + ml) * 3 + lab]
                          + ps[(256 + ml) * 3 + lab] + ps[(384 + ml) * 3 + lab];
            part[(size_t)blockIdx.y * M * 3 + (size_t)(m0 + ml) * 3 + lab] = s;
        }
    }
}

// ---------------------------------------------------------------------------
// Kernel 4: deterministic partial-logit reduction (+b3)
// ---------------------------------------------------------------------------
__global__ __launch_bounds__(256) void logits_kernel(
    const float* __restrict__ part,
    const float* __restrict__ b3,
    float* __restrict__ out, int M)
{
    const int idx = blockIdx.x * 256 + threadIdx.x;
    if (idx >= M * 3) return;
    const int lab = idx % 3;
    float s = b3[lab];
    #pragma unroll
    for (int by = 0; by < 8; by++)
        s += part[(size_t)by * M * 3 + idx];
    out[idx] = s;
}

// ---------------------------------------------------------------------------
// Launcher
// ---------------------------------------------------------------------------
extern "C" void kernel_launch(void* const* d_in, const int* in_sizes, int n_in,
                              void* d_out, int out_size)
{
    const float* features = (const float*)d_in[0];
    const float* lines    = (const float*)d_in[1];
    const float* w_fc1    = (const float*)d_in[2];
    const float* b_fc1    = (const float*)d_in[3];
    const float* w1       = (const float*)d_in[4];
    const float* b1       = (const float*)d_in[5];
    const float* w2       = (const float*)d_in[6];
    const float* b2       = (const float*)d_in[7];
    const float* w3       = (const float*)d_in[8];
    const float* b3       = (const float*)d_in[9];
    float* out = (float*)d_out;

    const int nlines = in_sizes[1] / 4;   // 16000

    float *loi, *part;
    __half *fhi, *flo, *x1hi, *x1lo, *w1h, *w2h;
    cudaGetSymbolAddress((void**)&loi,  g_loi);
    cudaGetSymbolAddress((void**)&fhi,  g_feat_hi);
    cudaGetSymbolAddress((void**)&flo,  g_feat_lo);
    cudaGetSymbolAddress((void**)&x1hi, g_x1_hi);
    cudaGetSymbolAddress((void**)&x1lo, g_x1_lo);
    cudaGetSymbolAddress((void**)&part, g_part);
    cudaGetSymbolAddress((void**)&w1h,  g_w1h);
    cudaGetSymbolAddress((void**)&w2h,  g_w2h);

    cudaFuncSetAttribute(fc_mma_kernel<1>,
                         cudaFuncAttributeMaxDynamicSharedMemorySize, SMEM_FC);
    cudaFuncSetAttribute(fc_mma_kernel<2>,
                         cudaFuncAttributeMaxDynamicSharedMemorySize, SMEM_FC);

    // 0. weight fp16 planes (single launch for both)
    convert_w_kernel<<<2 * DFC * DFC / 1024, 256>>>(w1, w1h, w2, w2h, DFC * DFC);

    // 1. LOI head
    loi_kernel<<<HW / 128, 256>>>(features, w_fc1, b_fc1, loi);

    // 2. Line pooling -> fp16 hi/lo planes
    pool_kernel<<<nlines, 128>>>(lines, loi, fhi, flo, nlines);

    // 3. MLP on tensor cores (2-product fp16); fc2 fuses 3-label output
    const int mb = nlines / 128;          // 125
    fc_mma_kernel<1><<<dim3(mb, DFC / 128), 256, SMEM_FC>>>(
        fhi, flo, w1h, b1, x1hi, x1lo, nullptr, nullptr, nlines, DFC, DFC);
    fc_mma_kernel<2><<<dim3(mb, DFC / 128), 256, SMEM_FC>>>(
        x1hi, x1lo, w2h, b2, nullptr, nullptr, w3, part, nlines, DFC, DFC);

    // 4. Reduce partials -> logits
    logits_kernel<<<(nlines * 3 + 255) / 256, 256>>>(part, b3, out, nlines);
}

// round 15
// speedup vs baseline: 1.5494x; 1.1370x over previous
#include <cuda_runtime.h>
#include <cuda_fp16.h>
#include <cstdint>
#include <math.h>

// ---------------------------------------------------------------------------
// Problem constants
// ---------------------------------------------------------------------------
#define HGT      128
#define WID      128
#define HW       (HGT * WID)
#define C_IN     256
#define DLOI     128
#define NPTS0    32
#define NPTS1    8
#define MAXLINES 16000
#define DFC      1024
#define NLAB     3

// ---------------------------------------------------------------------------
// Scratch (device globals)
// ---------------------------------------------------------------------------
__device__ __align__(256) float   g_loi [HW * DLOI];
__device__ __align__(256) __half  g_feat_hi[MAXLINES * DFC];
__device__ __align__(256) __half  g_feat_lo[MAXLINES * DFC];
__device__ __align__(256) __half  g_x1_hi  [MAXLINES * DFC];
__device__ __align__(256) __half  g_x1_lo  [MAXLINES * DFC];
__device__ __align__(256) float   g_part[8 * MAXLINES * NLAB];
__device__ __align__(256) __half  g_w1h[DFC * DFC];
__device__ __align__(256) __half  g_w2h[DFC * DFC];

// ---------------------------------------------------------------------------
// Portable PTX helpers (baseline sm_80+ features; compile for plain sm_103)
// ---------------------------------------------------------------------------
__device__ __forceinline__ uint32_t smem_u32(const void* p) {
    uint32_t a;
    asm("{ .reg .u64 t; cvta.to.shared.u64 t, %1; cvt.u32.u64 %0, t; }"
        : "=r"(a) : "l"(p));
    return a;
}
// SW128 swizzle (128B rows): bits[6:4] ^= bits[9:7]
#define SWZ(o) ((o) ^ (((o) >> 3) & 0x70))

__device__ __forceinline__ void cp16(uint32_t dst, const void* src) {
    asm volatile("cp.async.cg.shared.global [%0], [%1], 16;"
                 :: "r"(dst), "l"(src));
}
__device__ __forceinline__ void cp_commit() {
    asm volatile("cp.async.commit_group;");
}
__device__ __forceinline__ void ldsm4(uint32_t* r, uint32_t addr) {
    asm volatile("ldmatrix.sync.aligned.m8n8.x4.shared.b16 {%0,%1,%2,%3}, [%4];"
                 : "=r"(r[0]), "=r"(r[1]), "=r"(r[2]), "=r"(r[3]) : "r"(addr));
}
__device__ __forceinline__ void mma16816(float* c, const uint32_t* a,
                                         const uint32_t* b) {
    asm volatile(
        "mma.sync.aligned.m16n8k16.row.col.f32.f16.f16.f32 "
        "{%0,%1,%2,%3}, {%4,%5,%6,%7}, {%8,%9}, {%0,%1,%2,%3};"
        : "+f"(c[0]), "+f"(c[1]), "+f"(c[2]), "+f"(c[3])
        : "r"(a[0]), "r"(a[1]), "r"(a[2]), "r"(a[3]), "r"(b[0]), "r"(b[1]));
}

// ---------------------------------------------------------------------------
// Kernel 0: fp32 -> single fp16 plane for BOTH weight matrices
// ---------------------------------------------------------------------------
__global__ __launch_bounds__(256) void convert_w_kernel(
    const float* __restrict__ wa, __half* __restrict__ ha,
    const float* __restrict__ wb, __half* __restrict__ hb, int nhalf)
{
    int i = (blockIdx.x * 256 + threadIdx.x) * 4;
    const float* w; __half* h;
    if (i < nhalf) { w = wa; h = ha; }
    else           { w = wb; h = hb; i -= nhalf; }
    float4 v = *(const float4*)(w + i);
    __half2 p0 = __floats2half2_rn(v.x, v.y);
    __half2 p1 = __floats2half2_rn(v.z, v.w);
    *(uint2*)(h + i) = make_uint2(*(uint32_t*)&p0, *(uint32_t*)&p1);
}

// ---------------------------------------------------------------------------
// Kernel 1: LOI head GEMM (SIMT)
// ---------------------------------------------------------------------------
__global__ __launch_bounds__(256) void loi_kernel(
    const float* __restrict__ features,
    const float* __restrict__ w,
    const float* __restrict__ bias,
    float* __restrict__ out)
{
    __shared__ float As[16][132];
    __shared__ float Bs[16][132];
    const int t  = threadIdx.x;
    const int m0 = blockIdx.x * 128;
    const int tx = t & 15, ty = t >> 4;

    float acc[8][8] = {};

    for (int k0 = 0; k0 < C_IN; k0 += 16) {
        #pragma unroll
        for (int i = 0; i < 2; i++) {
            int idx = t + i * 256;
            int kk  = idx >> 5;
            int c4  = (idx & 31) << 2;
            float4 v = *(const float4*)(features + (size_t)(k0 + kk) * HW + m0 + c4);
            *(float4*)(&As[kk][c4]) = v;
        }
        #pragma unroll
        for (int i = 0; i < 2; i++) {
            int idx = t + i * 256;
            int n   = idx >> 2;
            int j4  = (idx & 3) << 2;
            float4 v = *(const float4*)(w + n * C_IN + k0 + j4);
            Bs[j4 + 0][n] = v.x; Bs[j4 + 1][n] = v.y;
            Bs[j4 + 2][n] = v.z; Bs[j4 + 3][n] = v.w;
        }
        __syncthreads();
        #pragma unroll
        for (int kk = 0; kk < 16; kk++) {
            float a[8], b[8];
            *(float4*)(a)     = *(const float4*)&As[kk][ty * 8];
            *(float4*)(a + 4) = *(const float4*)&As[kk][ty * 8 + 4];
            *(float4*)(b)     = *(const float4*)&Bs[kk][tx * 8];
            *(float4*)(b + 4) = *(const float4*)&Bs[kk][tx * 8 + 4];
            #pragma unroll
            for (int i = 0; i < 8; i++)
                #pragma unroll
                for (int j = 0; j < 8; j++)
                    acc[i][j] = fmaf(a[i], b[j], acc[i][j]);
        }
        __syncthreads();
    }

    float bv[8];
    *(float4*)(bv)     = *(const float4*)(bias + tx * 8);
    *(float4*)(bv + 4) = *(const float4*)(bias + tx * 8 + 4);
    #pragma unroll
    for (int i = 0; i < 8; i++) {
        const size_t row = (size_t)(m0 + ty * 8 + i) * DLOI + tx * 8;
        float4 o0, o1;
        o0.x = fmaxf(acc[i][0] + bv[0], 0.f); o0.y = fmaxf(acc[i][1] + bv[1], 0.f);
        o0.z = fmaxf(acc[i][2] + bv[2], 0.f); o0.w = fmaxf(acc[i][3] + bv[3], 0.f);
        o1.x = fmaxf(acc[i][4] + bv[4], 0.f); o1.y = fmaxf(acc[i][5] + bv[5], 0.f);
        o1.z = fmaxf(acc[i][6] + bv[6], 0.f); o1.w = fmaxf(acc[i][7] + bv[7], 0.f);
        *(float4*)(out + row)     = o0;
        *(float4*)(out + row + 4) = o1;
    }
}

// ---------------------------------------------------------------------------
// Kernel 2: line pooling (4 warps / line; proven) -> fp16 hi/lo planes
// ---------------------------------------------------------------------------
__global__ __launch_bounds__(128) void pool_kernel(
    const float* __restrict__ lines,
    const float* __restrict__ loi,
    __half* __restrict__ fhi,
    __half* __restrict__ flo,
    int nlines)
{
    __shared__ int   s_idx[4][NPTS0];
    __shared__ float s_wgt[4][NPTS0];
    __shared__ float s_out[NPTS1][DLOI];

    const int L    = blockIdx.x;
    const int t    = threadIdx.x;
    const int w    = t >> 5;
    const int lane = t & 31;
    if (L >= nlines) return;

    if (t < NPTS0) {
        const float4 q = ((const float4*)lines)[L];
        const float tt = (float)t / 31.0f;
        const float px = q.x * tt + q.z * (1.0f - tt) - 0.5f;
        const float py = q.y * tt + q.w * (1.0f - tt) - 0.5f;
        const float px0 = fminf(fmaxf(floorf(px), 0.0f), 127.0f);
        const float py0 = fminf(fmaxf(floorf(py), 0.0f), 127.0f);
        const float px1 = fminf(px0 + 1.0f, 127.0f);
        const float py1 = fminf(py0 + 1.0f, 127.0f);
        const int ix0 = (int)px0, iy0 = (int)py0, ix1 = (int)px1, iy1 = (int)py1;
        s_idx[0][t] = (iy0 * WID + ix0) * DLOI;
        s_idx[1][t] = (iy1 * WID + ix0) * DLOI;
        s_idx[2][t] = (iy0 * WID + ix1) * DLOI;
        s_idx[3][t] = (iy1 * WID + ix1) * DLOI;
        const float wy0 = py1 - py, wy1 = py - py0;
        const float wx0 = px1 - px, wx1 = px - px0;
        s_wgt[0][t] = wy0 * wx0;
        s_wgt[1][t] = wy1 * wx0;
        s_wgt[2][t] = wy0 * wx1;
        s_wgt[3][t] = wy1 * wx1;
    }
    __syncthreads();

    const int c4 = lane * 4;
    #pragma unroll
    for (int pp = 0; pp < 2; pp++) {
        const int p = w * 2 + pp;
        float mx = -1e30f, my = -1e30f, mz = -1e30f, mw = -1e30f;
        #pragma unroll
        for (int k = 0; k < 4; k++) {
            const int j = p * 4 + k;
            const int   i00 = s_idx[0][j], i10 = s_idx[1][j];
            const int   i01 = s_idx[2][j], i11 = s_idx[3][j];
            const float w00 = s_wgt[0][j], w10 = s_wgt[1][j];
            const float w01 = s_wgt[2][j], w11 = s_wgt[3][j];
            const float4 v00 = *(const float4*)(loi + i00 + c4);
            const float4 v10 = *(const float4*)(loi + i10 + c4);
            const float4 v01 = *(const float4*)(loi + i01 + c4);
            const float4 v11 = *(const float4*)(loi + i11 + c4);
            float vx, vy, vz, vw;
            vx = fmaf(w00, v00.x, fmaf(w10, v10.x, fmaf(w01, v01.x, w11 * v11.x)));
            vy = fmaf(w00, v00.y, fmaf(w10, v10.y, fmaf(w01, v01.y, w11 * v11.y)));
            vz = fmaf(w00, v00.z, fmaf(w10, v10.z, fmaf(w01, v01.z, w11 * v11.z)));
            vw = fmaf(w00, v00.w, fmaf(w10, v10.w, fmaf(w01, v01.w, w11 * v11.w)));
            mx = fmaxf(mx, vx); my = fmaxf(my, vy);
            mz = fmaxf(mz, vz); mw = fmaxf(mw, vw);
        }
        *(float4*)(&s_out[p][c4]) = make_float4(mx, my, mz, mw);
    }
    __syncthreads();

    __half h[NPTS1], l[NPTS1];
    #pragma unroll
    for (int p = 0; p < NPTS1; p++) {
        const float v = s_out[p][t];
        __half hb = __float2half_rn(v);
        h[p] = hb;
        l[p] = __float2half_rn(v - __half2float(hb));
    }
    const size_t off = (size_t)L * DFC + t * NPTS1;
    *(uint4*)(fhi + off) = *(uint4*)h;
    *(uint4*)(flo + off) = *(uint4*)l;
}

// ---------------------------------------------------------------------------
// Kernel 3: HMMA fp16 FC layer. A = hi/lo fp16 (exact), W = single fp16.
//   D = Ahi*W + Alo*W  (fp32 accum). 256 thr, 8 warps (2M x 4N), tile 64x32.
//   NSTAGE=2 x 48KB -> 97KB smem -> 2 CTAs/SM (the whole point this round).
//   Staged fragment reuse keeps regs <= 128 for minBlocks=2.
//   MODE 1: out = hi/lo fp16 planes (fc1).
//   MODE 2: fused final layer — per-block partial logits (fc2+fc3).
// ---------------------------------------------------------------------------
#define KC      64
#define TILEB   16384            // 128 rows x 128B (64 fp16)
#define BUFB    (3 * TILEB)      // A_hi, A_lo, W
#define NSTAGE  2
#define SMEM_FC (1024 + NSTAGE * BUFB)

template<int MODE>
__global__ __launch_bounds__(256, 2)
void fc_mma_kernel(const __half* __restrict__ Ahi,
                   const __half* __restrict__ Alo,
                   const __half* __restrict__ W,
                   const float* __restrict__ bias,
                   __half* __restrict__ Chi,
                   __half* __restrict__ Clo,
                   const float* __restrict__ w3,
                   float* __restrict__ part,
                   int M, int N, int K)
{
    extern __shared__ char smem_raw[];
    const uint32_t sb   = smem_u32(smem_raw);
    const uint32_t bufu = (sb + 1023) & ~1023u;
    char* bufbase = smem_raw + (bufu - sb);

    const int t     = threadIdx.x;
    const int warp  = t >> 5, lane = t & 31;
    const int warpM = warp & 1;          // 2 warps along M (64 rows)
    const int warpN = warp >> 1;         // 4 warps along N (32 cols)
    const int m0    = blockIdx.x * 128;
    const int n0    = blockIdx.y * 128;

    const int ar   = (lane & 7) + ((lane >> 3) & 1) * 8;
    const int acb  = ((lane >> 4) & 1) * 16;
    const uint32_t axor = (uint32_t)((lane & 7) << 4);
    uint32_t aterm[4];
    #pragma unroll
    for (int mt = 0; mt < 4; mt++)
        aterm[mt] = (uint32_t)((warpM * 64 + mt * 16 + ar) * 128);
    const int bi  = lane >> 3;
    const int bcb = (bi & 1) * 16;
    uint32_t bterm[2];
    #pragma unroll
    for (int p = 0; p < 2; p++)
        bterm[p] = (uint32_t)((warpN * 32 + (2 * p + (bi >> 1)) * 8 + (lane & 7)) * 128);

    float acc[4][4][4] = {};

    auto load_chunk = [&](int c) {
        const uint32_t dbase = bufu + (uint32_t)(c & 1) * BUFB;
        const int k0 = c * KC;
        #pragma unroll
        for (int i = 0; i < 4; i++) {
            const int idx = t + i * 256;
            const int row = idx >> 3, g8 = (idx & 7) * 8;
            const uint32_t off = SWZ((uint32_t)(row * 128 + g8 * 2));
            const size_t ga = (size_t)(m0 + row) * K + k0 + g8;
            const size_t gw = (size_t)(n0 + row) * K + k0 + g8;
            cp16(dbase + off,             Ahi + ga);
            cp16(dbase + TILEB + off,     Alo + ga);
            cp16(dbase + 2 * TILEB + off, W + gw);
        }
        cp_commit();
    };

    const int nchunk = K / KC;   // 16
    load_chunk(0);

    for (int c = 0; c < nchunk; ++c) {
        if (c + 1 < nchunk) {
            load_chunk(c + 1);
            asm volatile("cp.async.wait_group 1;");
        } else {
            asm volatile("cp.async.wait_group 0;");
        }
        __syncthreads();                         // stage c ready for all warps

        const uint32_t base = bufu + (uint32_t)(c & 1) * BUFB;
        #pragma unroll
        for (int kk = 0; kk < 4; kk++) {
            const uint32_t acol = (uint32_t)(kk * 32 + acb) ^ axor;
            const uint32_t bcol = (uint32_t)(kk * 32 + bcb) ^ axor;

            uint32_t aF[4][4], bW[2][4];
            #pragma unroll
            for (int mt = 0; mt < 4; mt++)
                ldsm4(aF[mt], base + aterm[mt] + acol);              // A_hi
            #pragma unroll
            for (int p = 0; p < 2; p++)
                ldsm4(bW[p], base + 2 * TILEB + bterm[p] + bcol);    // W
            #pragma unroll
            for (int mt = 0; mt < 4; mt++)
                #pragma unroll
                for (int nt = 0; nt < 4; nt++)
                    mma16816(acc[mt][nt], aF[mt], &bW[nt >> 1][(nt & 1) * 2]);
            #pragma unroll
            for (int mt = 0; mt < 4; mt++)
                ldsm4(aF[mt], base + TILEB + aterm[mt] + acol);      // A_lo (reuse)
            #pragma unroll
            for (int mt = 0; mt < 4; mt++)
                #pragma unroll
                for (int nt = 0; nt < 4; nt++)
                    mma16816(acc[mt][nt], aF[mt], &bW[nt >> 1][(nt & 1) * 2]);
        }
        if (c + 1 < nchunk)
            __syncthreads();                     // compute(c) done before load(c+2)
    }

    const int qrow = lane >> 2;
    const int qcol = (lane & 3) * 2;

    if (MODE == 1) {
        #pragma unroll
        for (int nt = 0; nt < 4; nt++) {
            const int coln = n0 + warpN * 32 + nt * 8 + qcol;
            const float2 bv = *(const float2*)(bias + coln);
            #pragma unroll
            for (int mt = 0; mt < 4; mt++) {
                const int rown = m0 + warpM * 64 + mt * 16 + qrow;
                float v0 = fmaxf(acc[mt][nt][0] + bv.x, 0.f);
                float v1 = fmaxf(acc[mt][nt][1] + bv.y, 0.f);
                float v2 = fmaxf(acc[mt][nt][2] + bv.x, 0.f);
                float v3 = fmaxf(acc[mt][nt][3] + bv.y, 0.f);
                const size_t o0 = (size_t)rown * N + coln;
                const size_t o1 = (size_t)(rown + 8) * N + coln;
                __half h0 = __float2half_rn(v0), h1 = __float2half_rn(v1);
                __half h2 = __float2half_rn(v2), h3 = __float2half_rn(v3);
                __half l0 = __float2half_rn(v0 - __half2float(h0));
                __half l1 = __float2half_rn(v1 - __half2float(h1));
                __half l2 = __float2half_rn(v2 - __half2float(h2));
                __half l3 = __float2half_rn(v3 - __half2float(h3));
                __half2 ph0, ph1, pl0, pl1;
                ph0.x = h0; ph0.y = h1; ph1.x = h2; ph1.y = h3;
                pl0.x = l0; pl0.y = l1; pl1.x = l2; pl1.y = l3;
                *(__half2*)(Chi + o0) = ph0;
                *(__half2*)(Chi + o1) = ph1;
                *(__half2*)(Clo + o0) = pl0;
                *(__half2*)(Clo + o1) = pl1;
            }
        }
    } else {
        __syncthreads();    // all compute done before smem reuse
        float pr[4][2][3] = {};
        #pragma unroll
        for (int nt = 0; nt < 4; nt++) {
            const int coln = n0 + warpN * 32 + nt * 8 + qcol;
            const float2 bv = *(const float2*)(bias + coln);
            float w3v[3][2];
            #pragma unroll
            for (int lab = 0; lab < 3; lab++) {
                w3v[lab][0] = w3[lab * DFC + coln];
                w3v[lab][1] = w3[lab * DFC + coln + 1];
            }
            #pragma unroll
            for (int mt = 0; mt < 4; mt++) {
                float v0 = fmaxf(acc[mt][nt][0] + bv.x, 0.f);
                float v1 = fmaxf(acc[mt][nt][1] + bv.y, 0.f);
                float v2 = fmaxf(acc[mt][nt][2] + bv.x, 0.f);
                float v3 = fmaxf(acc[mt][nt][3] + bv.y, 0.f);
                #pragma unroll
                for (int lab = 0; lab < 3; lab++) {
                    pr[mt][0][lab] = fmaf(v0, w3v[lab][0],
                                     fmaf(v1, w3v[lab][1], pr[mt][0][lab]));
                    pr[mt][1][lab] = fmaf(v2, w3v[lab][0],
                                     fmaf(v3, w3v[lab][1], pr[mt][1][lab]));
                }
            }
        }
        #pragma unroll
        for (int mask = 1; mask <= 2; mask <<= 1)
            #pragma unroll
            for (int mt = 0; mt < 4; mt++)
                #pragma unroll
                for (int hh = 0; hh < 2; hh++)
                    #pragma unroll
                    for (int lab = 0; lab < 3; lab++)
                        pr[mt][hh][lab] +=
                            __shfl_xor_sync(0xffffffffu, pr[mt][hh][lab], mask);
        float* ps = (float*)bufbase;   // [4 warpN][128 m][3]
        if ((lane & 3) == 0) {
            #pragma unroll
            for (int mt = 0; mt < 4; mt++)
                #pragma unroll
                for (int hh = 0; hh < 2; hh++) {
                    const int ml = warpM * 64 + mt * 16 + hh * 8 + qrow;
                    #pragma unroll
                    for (int lab = 0; lab < 3; lab++)
                        ps[(warpN * 128 + ml) * 3 + lab] = pr[mt][hh][lab];
                }
        }
        __syncthreads();
        for (int idx = t; idx < 384; idx += 256) {
            const int ml = idx / 3, lab = idx - ml * 3;
            const float s = ps[ml * 3 + lab] + ps[(128 + ml) * 3 + lab]
                          + ps[(256 + ml) * 3 + lab] + ps[(384 + ml) * 3 + lab];
            part[(size_t)blockIdx.y * M * 3 + (size_t)(m0 + ml) * 3 + lab] = s;
        }
    }
}

// ---------------------------------------------------------------------------
// Kernel 4: deterministic partial-logit reduction (+b3)
// ---------------------------------------------------------------------------
__global__ __launch_bounds__(256) void logits_kernel(
    const float* __restrict__ part,
    const float* __restrict__ b3,
    float* __restrict__ out, int M)
{
    const int idx = blockIdx.x * 256 + threadIdx.x;
    if (idx >= M * 3) return;
    const int lab = idx % 3;
    float s = b3[lab];
    #pragma unroll
    for (int by = 0; by < 8; by++)
        s += part[(size_t)by * M * 3 + idx];
    out[idx] = s;
}

// ---------------------------------------------------------------------------
// Launcher
// ---------------------------------------------------------------------------
extern "C" void kernel_launch(void* const* d_in, const int* in_sizes, int n_in,
                              void* d_out, int out_size)
{
    const float* features = (const float*)d_in[0];
    const float* lines    = (const float*)d_in[1];
    const float* w_fc1    = (const float*)d_in[2];
    const float* b_fc1    = (const float*)d_in[3];
    const float* w1       = (const float*)d_in[4];
    const float* b1       = (const float*)d_in[5];
    const float* w2       = (const float*)d_in[6];
    const float* b2       = (const float*)d_in[7];
    const float* w3       = (const float*)d_in[8];
    const float* b3       = (const float*)d_in[9];
    float* out = (float*)d_out;

    const int nlines = in_sizes[1] / 4;   // 16000

    float *loi, *part;
    __half *fhi, *flo, *x1hi, *x1lo, *w1h, *w2h;
    cudaGetSymbolAddress((void**)&loi,  g_loi);
    cudaGetSymbolAddress((void**)&fhi,  g_feat_hi);
    cudaGetSymbolAddress((void**)&flo,  g_feat_lo);
    cudaGetSymbolAddress((void**)&x1hi, g_x1_hi);
    cudaGetSymbolAddress((void**)&x1lo, g_x1_lo);
    cudaGetSymbolAddress((void**)&part, g_part);
    cudaGetSymbolAddress((void**)&w1h,  g_w1h);
    cudaGetSymbolAddress((void**)&w2h,  g_w2h);

    cudaFuncSetAttribute(fc_mma_kernel<1>,
                         cudaFuncAttributeMaxDynamicSharedMemorySize, SMEM_FC);
    cudaFuncSetAttribute(fc_mma_kernel<2>,
                         cudaFuncAttributeMaxDynamicSharedMemorySize, SMEM_FC);

    // 0. weight fp16 planes (single launch for both)
    convert_w_kernel<<<2 * DFC * DFC / 1024, 256>>>(w1, w1h, w2, w2h, DFC * DFC);

    // 1. LOI head
    loi_kernel<<<HW / 128, 256>>>(features, w_fc1, b_fc1, loi);

    // 2. Line pooling -> fp16 hi/lo planes
    pool_kernel<<<nlines, 128>>>(lines, loi, fhi, flo, nlines);

    // 3. MLP on tensor cores (2-product fp16, 2 CTAs/SM); fc2 fuses output
    const int mb = nlines / 128;          // 125
    fc_mma_kernel<1><<<dim3(mb, DFC / 128), 256, SMEM_FC>>>(
        fhi, flo, w1h, b1, x1hi, x1lo, nullptr, nullptr, nlines, DFC, DFC);
    fc_mma_kernel<2><<<dim3(mb, DFC / 128), 256, SMEM_FC>>>(
        x1hi, x1lo, w2h, b2, nullptr, nullptr, w3, part, nlines, DFC, DFC);

    // 4. Reduce partials -> logits
    logits_kernel<<<(nlines * 3 + 255) / 256, 256>>>(part, b3, out, nlines);
}

// round 17
// speedup vs baseline: 2.3649x; 1.5264x over previous
#include <cuda_runtime.h>
#include <cuda_fp16.h>
#include <cstdint>
#include <math.h>

// ---------------------------------------------------------------------------
// Problem constants
// ---------------------------------------------------------------------------
#define HGT      128
#define WID      128
#define HW       (HGT * WID)
#define C_IN     256
#define DLOI     128
#define NPTS0    32
#define NPTS1    8
#define MAXLINES 16000
#define DFC      1024
#define NLAB     3

// ---------------------------------------------------------------------------
// Scratch (device globals)
// ---------------------------------------------------------------------------
__device__ __align__(256) float   g_loi [HW * DLOI];
__device__ __align__(256) __half  g_feat[MAXLINES * DFC];
__device__ __align__(256) __half  g_x1  [MAXLINES * DFC];
__device__ __align__(256) float   g_part[8 * MAXLINES * NLAB];
__device__ __align__(256) __half  g_w1h[DFC * DFC];
__device__ __align__(256) __half  g_w2h[DFC * DFC];

// ---------------------------------------------------------------------------
// Portable PTX helpers (baseline sm_80+ features; compile for plain sm_103)
// ---------------------------------------------------------------------------
__device__ __forceinline__ uint32_t smem_u32(const void* p) {
    uint32_t a;
    asm("{ .reg .u64 t; cvta.to.shared.u64 t, %1; cvt.u32.u64 %0, t; }"
        : "=r"(a) : "l"(p));
    return a;
}
// SW128 swizzle (128B rows): bits[6:4] ^= bits[9:7]
#define SWZ(o) ((o) ^ (((o) >> 3) & 0x70))

__device__ __forceinline__ void cp16(uint32_t dst, const void* src) {
    asm volatile("cp.async.cg.shared.global [%0], [%1], 16;"
                 :: "r"(dst), "l"(src));
}
__device__ __forceinline__ void cp_commit() {
    asm volatile("cp.async.commit_group;");
}
__device__ __forceinline__ void ldsm4(uint32_t* r, uint32_t addr) {
    asm volatile("ldmatrix.sync.aligned.m8n8.x4.shared.b16 {%0,%1,%2,%3}, [%4];"
                 : "=r"(r[0]), "=r"(r[1]), "=r"(r[2]), "=r"(r[3]) : "r"(addr));
}
__device__ __forceinline__ void mma16816(float* c, const uint32_t* a,
                                         const uint32_t* b) {
    asm volatile(
        "mma.sync.aligned.m16n8k16.row.col.f32.f16.f16.f32 "
        "{%0,%1,%2,%3}, {%4,%5,%6,%7}, {%8,%9}, {%0,%1,%2,%3};"
        : "+f"(c[0]), "+f"(c[1]), "+f"(c[2]), "+f"(c[3])
        : "r"(a[0]), "r"(a[1]), "r"(a[2]), "r"(a[3]), "r"(b[0]), "r"(b[1]));
}

// ---------------------------------------------------------------------------
// Kernel 0: fp32 -> single fp16 plane for BOTH weight matrices
// ---------------------------------------------------------------------------
__global__ __launch_bounds__(256) void convert_w_kernel(
    const float* __restrict__ wa, __half* __restrict__ ha,
    const float* __restrict__ wb, __half* __restrict__ hb, int nhalf)
{
    int i = (blockIdx.x * 256 + threadIdx.x) * 4;
    const float* w; __half* h;
    if (i < nhalf) { w = wa; h = ha; }
    else           { w = wb; h = hb; i -= nhalf; }
    float4 v = *(const float4*)(w + i);
    __half2 p0 = __floats2half2_rn(v.x, v.y);
    __half2 p1 = __floats2half2_rn(v.z, v.w);
    *(uint2*)(h + i) = make_uint2(*(uint32_t*)&p0, *(uint32_t*)&p1);
}

// ---------------------------------------------------------------------------
// Kernel 1: LOI head GEMM (SIMT)
// ---------------------------------------------------------------------------
__global__ __launch_bounds__(256) void loi_kernel(
    const float* __restrict__ features,
    const float* __restrict__ w,
    const float* __restrict__ bias,
    float* __restrict__ out)
{
    __shared__ float As[16][132];
    __shared__ float Bs[16][132];
    const int t  = threadIdx.x;
    const int m0 = blockIdx.x * 128;
    const int tx = t & 15, ty = t >> 4;

    float acc[8][8] = {};

    for (int k0 = 0; k0 < C_IN; k0 += 16) {
        #pragma unroll
        for (int i = 0; i < 2; i++) {
            int idx = t + i * 256;
            int kk  = idx >> 5;
            int c4  = (idx & 31) << 2;
            float4 v = *(const float4*)(features + (size_t)(k0 + kk) * HW + m0 + c4);
            *(float4*)(&As[kk][c4]) = v;
        }
        #pragma unroll
        for (int i = 0; i < 2; i++) {
            int idx = t + i * 256;
            int n   = idx >> 2;
            int j4  = (idx & 3) << 2;
            float4 v = *(const float4*)(w + n * C_IN + k0 + j4);
            Bs[j4 + 0][n] = v.x; Bs[j4 + 1][n] = v.y;
            Bs[j4 + 2][n] = v.z; Bs[j4 + 3][n] = v.w;
        }
        __syncthreads();
        #pragma unroll
        for (int kk = 0; kk < 16; kk++) {
            float a[8], b[8];
            *(float4*)(a)     = *(const float4*)&As[kk][ty * 8];
            *(float4*)(a + 4) = *(const float4*)&As[kk][ty * 8 + 4];
            *(float4*)(b)     = *(const float4*)&Bs[kk][tx * 8];
            *(float4*)(b + 4) = *(const float4*)&Bs[kk][tx * 8 + 4];
            #pragma unroll
            for (int i = 0; i < 8; i++)
                #pragma unroll
                for (int j = 0; j < 8; j++)
                    acc[i][j] = fmaf(a[i], b[j], acc[i][j]);
        }
        __syncthreads();
    }

    float bv[8];
    *(float4*)(bv)     = *(const float4*)(bias + tx * 8);
    *(float4*)(bv + 4) = *(const float4*)(bias + tx * 8 + 4);
    #pragma unroll
    for (int i = 0; i < 8; i++) {
        const size_t row = (size_t)(m0 + ty * 8 + i) * DLOI + tx * 8;
        float4 o0, o1;
        o0.x = fmaxf(acc[i][0] + bv[0], 0.f); o0.y = fmaxf(acc[i][1] + bv[1], 0.f);
        o0.z = fmaxf(acc[i][2] + bv[2], 0.f); o0.w = fmaxf(acc[i][3] + bv[3], 0.f);
        o1.x = fmaxf(acc[i][4] + bv[4], 0.f); o1.y = fmaxf(acc[i][5] + bv[5], 0.f);
        o1.z = fmaxf(acc[i][6] + bv[6], 0.f); o1.w = fmaxf(acc[i][7] + bv[7], 0.f);
        *(float4*)(out + row)     = o0;
        *(float4*)(out + row + 4) = o1;
    }
}

// ---------------------------------------------------------------------------
// Kernel 2: line pooling (4 warps / line; proven) -> single fp16 plane
// ---------------------------------------------------------------------------
__global__ __launch_bounds__(128) void pool_kernel(
    const float* __restrict__ lines,
    const float* __restrict__ loi,
    __half* __restrict__ feat,
    int nlines)
{
    __shared__ int   s_idx[4][NPTS0];
    __shared__ float s_wgt[4][NPTS0];
    __shared__ float s_out[NPTS1][DLOI];

    const int L    = blockIdx.x;
    const int t    = threadIdx.x;
    const int w    = t >> 5;
    const int lane = t & 31;
    if (L >= nlines) return;

    if (t < NPTS0) {
        const float4 q = ((const float4*)lines)[L];
        const float tt = (float)t / 31.0f;
        const float px = q.x * tt + q.z * (1.0f - tt) - 0.5f;
        const float py = q.y * tt + q.w * (1.0f - tt) - 0.5f;
        const float px0 = fminf(fmaxf(floorf(px), 0.0f), 127.0f);
        const float py0 = fminf(fmaxf(floorf(py), 0.0f), 127.0f);
        const float px1 = fminf(px0 + 1.0f, 127.0f);
        const float py1 = fminf(py0 + 1.0f, 127.0f);
        const int ix0 = (int)px0, iy0 = (int)py0, ix1 = (int)px1, iy1 = (int)py1;
        s_idx[0][t] = (iy0 * WID + ix0) * DLOI;
        s_idx[1][t] = (iy1 * WID + ix0) * DLOI;
        s_idx[2][t] = (iy0 * WID + ix1) * DLOI;
        s_idx[3][t] = (iy1 * WID + ix1) * DLOI;
        const float wy0 = py1 - py, wy1 = py - py0;
        const float wx0 = px1 - px, wx1 = px - px0;
        s_wgt[0][t] = wy0 * wx0;
        s_wgt[1][t] = wy1 * wx0;
        s_wgt[2][t] = wy0 * wx1;
        s_wgt[3][t] = wy1 * wx1;
    }
    __syncthreads();

    const int c4 = lane * 4;
    #pragma unroll
    for (int pp = 0; pp < 2; pp++) {
        const int p = w * 2 + pp;
        float mx = -1e30f, my = -1e30f, mz = -1e30f, mw = -1e30f;
        #pragma unroll
        for (int k = 0; k < 4; k++) {
            const int j = p * 4 + k;
            const int   i00 = s_idx[0][j], i10 = s_idx[1][j];
            const int   i01 = s_idx[2][j], i11 = s_idx[3][j];
            const float w00 = s_wgt[0][j], w10 = s_wgt[1][j];
            const float w01 = s_wgt[2][j], w11 = s_wgt[3][j];
            const float4 v00 = *(const float4*)(loi + i00 + c4);
            const float4 v10 = *(const float4*)(loi + i10 + c4);
            const float4 v01 = *(const float4*)(loi + i01 + c4);
            const float4 v11 = *(const float4*)(loi + i11 + c4);
            float vx, vy, vz, vw;
            vx = fmaf(w00, v00.x, fmaf(w10, v10.x, fmaf(w01, v01.x, w11 * v11.x)));
            vy = fmaf(w00, v00.y, fmaf(w10, v10.y, fmaf(w01, v01.y, w11 * v11.y)));
            vz = fmaf(w00, v00.z, fmaf(w10, v10.z, fmaf(w01, v01.z, w11 * v11.z)));
            vw = fmaf(w00, v00.w, fmaf(w10, v10.w, fmaf(w01, v01.w, w11 * v11.w)));
            mx = fmaxf(mx, vx); my = fmaxf(my, vy);
            mz = fmaxf(mz, vz); mw = fmaxf(mw, vw);
        }
        *(float4*)(&s_out[p][c4]) = make_float4(mx, my, mz, mw);
    }
    __syncthreads();

    __half h[NPTS1];
    #pragma unroll
    for (int p = 0; p < NPTS1; p++)
        h[p] = __float2half_rn(s_out[p][t]);
    const size_t off = (size_t)L * DFC + t * NPTS1;
    *(uint4*)(feat + off) = *(uint4*)h;
}

// ---------------------------------------------------------------------------
// Kernel 3: HMMA fp16 FC layer. A = fp16, W = fp16, fp32 accumulate.
//   256 thr, 8 warps (2M x 4N), warp tile 64x32.
//   NSTAGE=3 x 32KB -> 97KB smem -> 2 CTAs/SM, single sync per chunk.
//   MODE 1: out = fp16 (fc1).  MODE 2: fused final layer partials (fc2+fc3).
// ---------------------------------------------------------------------------
#define KC      64
#define TILEB   16384            // 128 rows x 128B (64 fp16)
#define BUFB    (2 * TILEB)      // A, W
#define NSTAGE  3
#define SMEM_FC (1024 + NSTAGE * BUFB)

template<int MODE>
__global__ __launch_bounds__(256, 2)
void fc_mma_kernel(const __half* __restrict__ A,
                   const __half* __restrict__ W,
                   const float* __restrict__ bias,
                   __half* __restrict__ C,
                   const float* __restrict__ w3,
                   float* __restrict__ part,
                   int M, int N, int K)
{
    extern __shared__ char smem_raw[];
    const uint32_t sb   = smem_u32(smem_raw);
    const uint32_t bufu = (sb + 1023) & ~1023u;
    char* bufbase = smem_raw + (bufu - sb);

    const int t     = threadIdx.x;
    const int warp  = t >> 5, lane = t & 31;
    const int warpM = warp & 1;          // 2 warps along M (64 rows)
    const int warpN = warp >> 1;         // 4 warps along N (32 cols)
    const int m0    = blockIdx.x * 128;
    const int n0    = blockIdx.y * 128;

    const int ar   = (lane & 7) + ((lane >> 3) & 1) * 8;
    const int acb  = ((lane >> 4) & 1) * 16;
    const uint32_t axor = (uint32_t)((lane & 7) << 4);
    uint32_t aterm[4];
    #pragma unroll
    for (int mt = 0; mt < 4; mt++)
        aterm[mt] = (uint32_t)((warpM * 64 + mt * 16 + ar) * 128);
    const int bi  = lane >> 3;
    const int bcb = (bi & 1) * 16;
    uint32_t bterm[2];
    #pragma unroll
    for (int p = 0; p < 2; p++)
        bterm[p] = (uint32_t)((warpN * 32 + (2 * p + (bi >> 1)) * 8 + (lane & 7)) * 128);

    float acc[4][4][4] = {};

    auto load_chunk = [&](int c) {
        const uint32_t dbase = bufu + (uint32_t)(c % NSTAGE) * BUFB;
        const int k0 = c * KC;
        #pragma unroll
        for (int i = 0; i < 4; i++) {
            const int idx = t + i * 256;
            const int row = idx >> 3, g8 = (idx & 7) * 8;
            const uint32_t off = SWZ((uint32_t)(row * 128 + g8 * 2));
            cp16(dbase + off,         A + (size_t)(m0 + row) * K + k0 + g8);
            cp16(dbase + TILEB + off, W + (size_t)(n0 + row) * K + k0 + g8);
        }
        cp_commit();
    };

    const int nchunk = K / KC;   // 16
    load_chunk(0);
    load_chunk(1);

    for (int c = 0; c < nchunk; ++c) {
        if (c + 1 < nchunk) asm volatile("cp.async.wait_group 1;");
        else                asm volatile("cp.async.wait_group 0;");
        __syncthreads();                        // stage c ready; compute c-1 done
        if (c + 2 < nchunk) load_chunk(c + 2);  // overwrites stage c-1

        const uint32_t base = bufu + (uint32_t)(c % NSTAGE) * BUFB;
        #pragma unroll
        for (int kk = 0; kk < 4; kk++) {
            const uint32_t acol = (uint32_t)(kk * 32 + acb) ^ axor;
            const uint32_t bcol = (uint32_t)(kk * 32 + bcb) ^ axor;

            uint32_t aF[4][4], bW[2][4];
            #pragma unroll
            for (int mt = 0; mt < 4; mt++)
                ldsm4(aF[mt], base + aterm[mt] + acol);
            #pragma unroll
            for (int p = 0; p < 2; p++)
                ldsm4(bW[p], base + TILEB + bterm[p] + bcol);
            #pragma unroll
            for (int mt = 0; mt < 4; mt++)
                #pragma unroll
                for (int nt = 0; nt < 4; nt++)
                    mma16816(acc[mt][nt], aF[mt], &bW[nt >> 1][(nt & 1) * 2]);
        }
    }

    const int qrow = lane >> 2;
    const int qcol = (lane & 3) * 2;

    if (MODE == 1) {
        #pragma unroll
        for (int nt = 0; nt < 4; nt++) {
            const int coln = n0 + warpN * 32 + nt * 8 + qcol;
            const float2 bv = *(const float2*)(bias + coln);
            #pragma unroll
            for (int mt = 0; mt < 4; mt++) {
                const int rown = m0 + warpM * 64 + mt * 16 + qrow;
                float v0 = fmaxf(acc[mt][nt][0] + bv.x, 0.f);
                float v1 = fmaxf(acc[mt][nt][1] + bv.y, 0.f);
                float v2 = fmaxf(acc[mt][nt][2] + bv.x, 0.f);
                float v3 = fmaxf(acc[mt][nt][3] + bv.y, 0.f);
                __half2 p0, p1;
                p0.x = __float2half_rn(v0); p0.y = __float2half_rn(v1);
                p1.x = __float2half_rn(v2); p1.y = __float2half_rn(v3);
                *(__half2*)(C + (size_t)rown * N + coln)       = p0;
                *(__half2*)(C + (size_t)(rown + 8) * N + coln) = p1;
            }
        }
    } else {
        __syncthreads();    // all compute done before smem reuse
        float pr[4][2][3] = {};
        #pragma unroll
        for (int nt = 0; nt < 4; nt++) {
            const int coln = n0 + warpN * 32 + nt * 8 + qcol;
            const float2 bv = *(const float2*)(bias + coln);
            float w3v[3][2];
            #pragma unroll
            for (int lab = 0; lab < 3; lab++) {
                w3v[lab][0] = w3[lab * DFC + coln];
                w3v[lab][1] = w3[lab * DFC + coln + 1];
            }
            #pragma unroll
            for (int mt = 0; mt < 4; mt++) {
                float v0 = fmaxf(acc[mt][nt][0] + bv.x, 0.f);
                float v1 = fmaxf(acc[mt][nt][1] + bv.y, 0.f);
                float v2 = fmaxf(acc[mt][nt][2] + bv.x, 0.f);
                float v3 = fmaxf(acc[mt][nt][3] + bv.y, 0.f);
                #pragma unroll
                for (int lab = 0; lab < 3; lab++) {
                    pr[mt][0][lab] = fmaf(v0, w3v[lab][0],
                                     fmaf(v1, w3v[lab][1], pr[mt][0][lab]));
                    pr[mt][1][lab] = fmaf(v2, w3v[lab][0],
                                     fmaf(v3, w3v[lab][1], pr[mt][1][lab]));
                }
            }
        }
        #pragma unroll
        for (int mask = 1; mask <= 2; mask <<= 1)
            #pragma unroll
            for (int mt = 0; mt < 4; mt++)
                #pragma unroll
                for (int hh = 0; hh < 2; hh++)
                    #pragma unroll
                    for (int lab = 0; lab < 3; lab++)
                        pr[mt][hh][lab] +=
                            __shfl_xor_sync(0xffffffffu, pr[mt][hh][lab], mask);
        float* ps = (float*)bufbase;   // [4 warpN][128 m][3]
        if ((lane & 3) == 0) {
            #pragma unroll
            for (int mt = 0; mt < 4; mt++)
                #pragma unroll
                for (int hh = 0; hh < 2; hh++) {
                    const int ml = warpM * 64 + mt * 16 + hh * 8 + qrow;
                    #pragma unroll
                    for (int lab = 0; lab < 3; lab++)
                        ps[(warpN * 128 + ml) * 3 + lab] = pr[mt][hh][lab];
                }
        }
        __syncthreads();
        for (int idx = t; idx < 384; idx += 256) {
            const int ml = idx / 3, lab = idx - ml * 3;
            const float s = ps[ml * 3 + lab] + ps[(128 + ml) * 3 + lab]
                          + ps[(256 + ml) * 3 + lab] + ps[(384 + ml) * 3 + lab];
            part[(size_t)blockIdx.y * M * 3 + (size_t)(m0 + ml) * 3 + lab] = s;
        }
    }
}

// ---------------------------------------------------------------------------
// Kernel 4: deterministic partial-logit reduction (+b3)
// ---------------------------------------------------------------------------
__global__ __launch_bounds__(256) void logits_kernel(
    const float* __restrict__ part,
    const float* __restrict__ b3,
    float* __restrict__ out, int M)
{
    const int idx = blockIdx.x * 256 + threadIdx.x;
    if (idx >= M * 3) return;
    const int lab = idx % 3;
    float s = b3[lab];
    #pragma unroll
    for (int by = 0; by < 8; by++)
        s += part[(size_t)by * M * 3 + idx];
    out[idx] = s;
}

// ---------------------------------------------------------------------------
// Launcher
// ---------------------------------------------------------------------------
extern "C" void kernel_launch(void* const* d_in, const int* in_sizes, int n_in,
                              void* d_out, int out_size)
{
    const float* features = (const float*)d_in[0];
    const float* lines    = (const float*)d_in[1];
    const float* w_fc1    = (const float*)d_in[2];
    const float* b_fc1    = (const float*)d_in[3];
    const float* w1       = (const float*)d_in[4];
    const float* b1       = (const float*)d_in[5];
    const float* w2       = (const float*)d_in[6];
    const float* b2       = (const float*)d_in[7];
    const float* w3       = (const float*)d_in[8];
    const float* b3       = (const float*)d_in[9];
    float* out = (float*)d_out;

    const int nlines = in_sizes[1] / 4;   // 16000

    float *loi, *part;
    __half *feat, *x1, *w1h, *w2h;
    cudaGetSymbolAddress((void**)&loi,  g_loi);
    cudaGetSymbolAddress((void**)&feat, g_feat);
    cudaGetSymbolAddress((void**)&x1,   g_x1);
    cudaGetSymbolAddress((void**)&part, g_part);
    cudaGetSymbolAddress((void**)&w1h,  g_w1h);
    cudaGetSymbolAddress((void**)&w2h,  g_w2h);

    cudaFuncSetAttribute(fc_mma_kernel<1>,
                         cudaFuncAttributeMaxDynamicSharedMemorySize, SMEM_FC);
    cudaFuncSetAttribute(fc_mma_kernel<2>,
                         cudaFuncAttributeMaxDynamicSharedMemorySize, SMEM_FC);

    // 0. weight fp16 planes (single launch for both)
    convert_w_kernel<<<2 * DFC * DFC / 1024, 256>>>(w1, w1h, w2, w2h, DFC * DFC);

    // 1. LOI head
    loi_kernel<<<HW / 128, 256>>>(features, w_fc1, b_fc1, loi);

    // 2. Line pooling -> fp16
    pool_kernel<<<nlines, 128>>>(lines, loi, feat, nlines);

    // 3. MLP on tensor cores (single-product fp16, 2 CTAs/SM, 3-stage)
    const int mb = nlines / 128;          // 125
    fc_mma_kernel<1><<<dim3(mb, DFC / 128), 256, SMEM_FC>>>(
        feat, w1h, b1, x1, nullptr, nullptr, nlines, DFC, DFC);
    fc_mma_kernel<2><<<dim3(mb, DFC / 128), 256, SMEM_FC>>>(
        x1, w2h, b2, nullptr, w3, part, nlines, DFC, DFC);

    // 4. Reduce partials -> logits
    logits_kernel<<<(nlines * 3 + 255) / 256, 256>>>(part, b3, out, nlines);
}